// round 2
// baseline (speedup 1.0000x reference)
#include <cuda_runtime.h>
#include <math.h>

#define BB 8
#define NN 2048
#define EE 128
#define HH 4

// ---------------- scratch (device globals; no runtime allocation) ----------
static __device__ float g_info[(size_t)BB * NN * NN];           // 134 MB
static __device__ float g_emb [(size_t)BB * NN * EE];
static __device__ float g_q   [(size_t)BB * HH * NN * EE];
static __device__ float g_v   [(size_t)BB * HH * NN * EE];
static __device__ float g_mt  [(size_t)BB * HH * NN * EE];      // (info @ v) = (v^T info)^T
static __device__ float g_attn[(size_t)BB * HH * NN * NN];      // 537 MB
static __device__ float g_hcat[(size_t)BB * NN * HH * EE];

// ---------------------------------------------------------------------------
// Generic tiled fp32 GEMM: C[M x Nn] = epi( A[M x K] * op(B) , bias, alpha )
//   TRANSB=1 : B is [Nn x K] row-major  (C = A * B^T)
//   TRANSB=0 : B is [K x Nn] row-major  (C = A * B)
//   EPI: 0 = none, 1 = +bias[n], 2 = tanh(acc*alpha), 3 = relu(acc+bias[n])
// Block tile 128x128, BK=8, 256 threads, 8x8 per thread.
// Requires: M % 128 == 0, Nn % 128 == 0, K % 8 == 0 (true for all stages).
// ---------------------------------------------------------------------------
template <int TRANSB, int EPI>
__global__ void __launch_bounds__(256)
gemm_k(const float* __restrict__ A, size_t sA,
       const float* __restrict__ Bm, size_t sB,
       const float* __restrict__ bias,
       float* __restrict__ C, size_t sC, int ldc,
       int M, int Nn, int K, float alpha)
{
    __shared__ float As[8][132];
    __shared__ float Bs[8][132];

    const int t    = threadIdx.x;
    const int tx   = t & 15;
    const int ty   = t >> 4;
    const int mblk = blockIdx.y * 128;
    const int nblk = blockIdx.x * 128;
    const int z    = blockIdx.z;

    A  += (size_t)z * sA;
    Bm += (size_t)z * sB;
    C  += (size_t)z * sC;

    // global-load mapping: each thread loads one float4 of A (and of B)
    const int arow = t >> 1;        // 0..127 (tile row)
    const int acol = (t & 1) * 4;   // 0 or 4 (k offset)
    const float* Aptr = A + (size_t)(mblk + arow) * K + acol;

    const float* Bptr;
    int brow = 0, bcol = 0;
    if (TRANSB) {
        Bptr = Bm + (size_t)(nblk + arow) * K + acol;   // B [Nn x K]
    } else {
        brow = t >> 5;              // 0..7 (k)
        bcol = (t & 31) * 4;        // 0..124 (n)
        Bptr = Bm + (size_t)brow * Nn + nblk + bcol;    // B [K x Nn]
    }

    float acc[8][8];
#pragma unroll
    for (int i = 0; i < 8; i++)
#pragma unroll
        for (int j = 0; j < 8; j++) acc[i][j] = 0.f;

    for (int kk = 0; kk < K; kk += 8) {
        float4 av = *(const float4*)(Aptr + kk);
        float4 bv;
        if (TRANSB) bv = *(const float4*)(Bptr + kk);
        else        bv = *(const float4*)(Bptr + (size_t)kk * Nn);

        __syncthreads();   // previous tile consumed
        As[acol + 0][arow] = av.x;
        As[acol + 1][arow] = av.y;
        As[acol + 2][arow] = av.z;
        As[acol + 3][arow] = av.w;
        if (TRANSB) {
            Bs[acol + 0][arow] = bv.x;
            Bs[acol + 1][arow] = bv.y;
            Bs[acol + 2][arow] = bv.z;
            Bs[acol + 3][arow] = bv.w;
        } else {
            *(float4*)&Bs[brow][bcol] = bv;
        }
        __syncthreads();

#pragma unroll
        for (int k = 0; k < 8; k++) {
            float a[8], b[8];
            *(float4*)&a[0] = *(const float4*)&As[k][ty * 8];
            *(float4*)&a[4] = *(const float4*)&As[k][ty * 8 + 4];
            *(float4*)&b[0] = *(const float4*)&Bs[k][tx * 8];
            *(float4*)&b[4] = *(const float4*)&Bs[k][tx * 8 + 4];
#pragma unroll
            for (int i = 0; i < 8; i++)
#pragma unroll
                for (int j = 0; j < 8; j++)
                    acc[i][j] = fmaf(a[i], b[j], acc[i][j]);
        }
    }

    // epilogue
    float bfrag[8];
    if (EPI == 1 || EPI == 3) {
#pragma unroll
        for (int j = 0; j < 8; j++) bfrag[j] = __ldg(&bias[nblk + tx * 8 + j]);
    }

#pragma unroll
    for (int i = 0; i < 8; i++) {
        size_t row = (size_t)(mblk + ty * 8 + i) * ldc + nblk + tx * 8;
        float o[8];
#pragma unroll
        for (int j = 0; j < 8; j++) {
            float vv = acc[i][j];
            if (EPI == 1) vv += bfrag[j];
            else if (EPI == 2) vv = tanhf(vv * alpha);
            else if (EPI == 3) { vv += bfrag[j]; vv = vv > 0.f ? vv : 0.f; }
            o[j] = vv;
        }
        *(float4*)(C + row)     = make_float4(o[0], o[1], o[2], o[3]);
        *(float4*)(C + row + 4) = make_float4(o[4], o[5], o[6], o[7]);
    }
}

// ---------------------------------------------------------------------------
extern "C" void kernel_launch(void* const* d_in, const int* in_sizes, int n_in,
                              void* d_out, int out_size)
{
    const float* x   = (const float*)d_in[0];   // [B,N,DF]
    const float* W1  = (const float*)d_in[1];   // [E,N]
    const float* b1  = (const float*)d_in[2];   // [E]
    const float* wqW = (const float*)d_in[3];   // [H,E,E]
    const float* wqb = (const float*)d_in[4];   // [H,E]
    // d_in[5], d_in[6]: wk_W / wk_b — dead in the reference (k unused); skipped
    const float* wvW = (const float*)d_in[7];   // [H,E,E]
    const float* wvb = (const float*)d_in[8];   // [H,E]
    const float* W2  = (const float*)d_in[9];   // [E, H*E]
    const float* b2  = (const float*)d_in[10];  // [E]
    float* out = (float*)d_out;

    float *info, *emb, *q, *v, *mt, *attn, *hcat;
    cudaGetSymbolAddress((void**)&info, g_info);
    cudaGetSymbolAddress((void**)&emb,  g_emb);
    cudaGetSymbolAddress((void**)&q,    g_q);
    cudaGetSymbolAddress((void**)&v,    g_v);
    cudaGetSymbolAddress((void**)&mt,   g_mt);
    cudaGetSymbolAddress((void**)&attn, g_attn);
    cudaGetSymbolAddress((void**)&hcat, g_hcat);

    const dim3 blk(256);
    const float alpha = 0.08838834764831843f;   // 1/sqrt(128)

    // S1: info[b] = x_b @ x_b^T          [2048x2048], K=128
    gemm_k<1, 0><<<dim3(16, 16, BB), blk>>>(
        x, (size_t)NN * EE, x, (size_t)NN * EE, nullptr,
        info, (size_t)NN * NN, NN, NN, NN, EE, 0.f);

    // S2: emb[b] = info_b @ W1^T + b1    [2048x128], K=2048
    gemm_k<1, 1><<<dim3(1, 16, BB), blk>>>(
        info, (size_t)NN * NN, W1, 0, b1,
        emb, (size_t)NN * EE, EE, NN, EE, NN, 0.f);

    // S3: q,v per head: [2048x128] = emb_b @ W_h^T + b_h   K=128
    for (int h = 0; h < HH; h++) {
        gemm_k<1, 1><<<dim3(1, 16, BB), blk>>>(
            emb, (size_t)NN * EE, wqW + (size_t)h * EE * EE, 0, wqb + h * EE,
            q + (size_t)h * NN * EE, (size_t)HH * NN * EE, EE, NN, EE, EE, 0.f);
        gemm_k<1, 1><<<dim3(1, 16, BB), blk>>>(
            emb, (size_t)NN * EE, wvW + (size_t)h * EE * EE, 0, wvb + h * EE,
            v + (size_t)h * NN * EE, (size_t)HH * NN * EE, EE, NN, EE, EE, 0.f);
    }

    // S4: mt[b,h] = info_b @ v_bh   (= (v^T info)^T, info symmetric)  K=2048
    for (int h = 0; h < HH; h++) {
        gemm_k<0, 0><<<dim3(1, 16, BB), blk>>>(
            info, (size_t)NN * NN,
            v + (size_t)h * NN * EE, (size_t)HH * NN * EE, nullptr,
            mt + (size_t)h * NN * EE, (size_t)HH * NN * EE, EE, NN, EE, NN, 0.f);
    }

    // S5: attn[z] = tanh( (q_z @ mt_z^T) / sqrt(E) )   [2048x2048], K=128, z=b*H+h
    gemm_k<1, 2><<<dim3(16, 16, BB * HH), blk>>>(
        q, (size_t)NN * EE, mt, (size_t)NN * EE, nullptr,
        attn, (size_t)NN * NN, NN, NN, NN, EE, alpha);

    // S6: hcat[b, :, h*128:(h+1)*128] = attn_bh @ v_bh   K=2048
    for (int h = 0; h < HH; h++) {
        gemm_k<0, 0><<<dim3(1, 16, BB), blk>>>(
            attn + (size_t)h * NN * NN, (size_t)HH * NN * NN,
            v + (size_t)h * NN * EE, (size_t)HH * NN * EE, nullptr,
            hcat + (size_t)h * EE, (size_t)NN * HH * EE, HH * EE, NN, EE, NN, 0.f);
    }

    // S7: out[b] = relu( hcat_b @ W2^T + b2 )   [2048x128], K=512
    gemm_k<1, 3><<<dim3(1, 16, BB), blk>>>(
        hcat, (size_t)NN * HH * EE, W2, 0, b2,
        out, (size_t)NN * EE, EE, NN, EE, HH * EE, 0.f);
}

// round 4
// speedup vs baseline: 2.3596x; 2.3596x over previous
#include <cuda_runtime.h>
#include <cstdint>
#include <math.h>

#define BB 8
#define NN 2048
#define EE 128
#define HH 4

static __device__ float g_info[(size_t)BB * NN * NN];
static __device__ float g_emb [(size_t)BB * NN * EE];
static __device__ float g_q   [(size_t)BB * NN * (HH * EE)];
static __device__ float g_v   [(size_t)BB * NN * (HH * EE)];
static __device__ float g_vt  [(size_t)BB * HH * EE * NN];
static __device__ float g_mt  [(size_t)BB * HH * NN * EE];
static __device__ float g_attn[(size_t)BB * HH * NN * NN];
static __device__ float g_hcat[(size_t)BB * NN * (HH * EE)];

__device__ __forceinline__ uint32_t smem_u32(const void* p) {
    uint32_t a;
    asm("{ .reg .u64 t; cvta.to.shared.u64 t, %1; cvt.u32.u64 %0, t; }" : "=r"(a) : "l"(p));
    return a;
}
__device__ __forceinline__ uint32_t sw64(uint32_t o) { return o ^ ((o >> 3) & 0x30); }

__device__ __forceinline__ void ldmx4(uint32_t* r, uint32_t addr) {
    asm volatile("ldmatrix.sync.aligned.m8n8.x4.shared.b16 {%0,%1,%2,%3}, [%4];"
                 : "=r"(r[0]), "=r"(r[1]), "=r"(r[2]), "=r"(r[3]) : "r"(addr));
}
__device__ __forceinline__ void mma16816(float* d, const uint32_t* a, const uint32_t* b) {
    asm volatile("mma.sync.aligned.m16n8k16.row.col.f32.bf16.bf16.f32 "
                 "{%0,%1,%2,%3}, {%4,%5,%6,%7}, {%8,%9}, {%0,%1,%2,%3};"
                 : "+f"(d[0]), "+f"(d[1]), "+f"(d[2]), "+f"(d[3])
                 : "r"(a[0]), "r"(a[1]), "r"(a[2]), "r"(a[3]), "r"(b[0]), "r"(b[1]));
}

// exact truncation split of a float pair into packed bf16x2 limbs
template <int NL>
__device__ __forceinline__ void split2(float f0, float f1, uint32_t& o0, uint32_t& o1, uint32_t& o2) {
    uint32_t u0 = __float_as_uint(f0), u1 = __float_as_uint(f1);
    float a0 = __uint_as_float(u0 & 0xFFFF0000u), a1 = __uint_as_float(u1 & 0xFFFF0000u);
    float r0 = f0 - a0, r1 = f1 - a1;                      // exact
    uint32_t v0 = __float_as_uint(r0), v1 = __float_as_uint(r1);
    o0 = __byte_perm(u0, u1, 0x7632);
    o1 = __byte_perm(v0, v1, 0x7632);
    if (NL == 3) {
        float b0 = __uint_as_float(v0 & 0xFFFF0000u), b1 = __uint_as_float(v1 & 0xFFFF0000u);
        o2 = __byte_perm(__float_as_uint(r0 - b0), __float_as_uint(r1 - b1), 0x7632); // exact
    }
}

// ---------------------------------------------------------------------------
// C tile[128x128] = epi(A*B^T); A [M x K] (lda), B [Nn x K] (ldb), K-contiguous.
// bf16 limb emulation: NL=3 -> 6 products (~fp32), NL=2 -> 3 products (~2^-16).
// BK=32 fp32; SMEM planes 128x32 bf16 (64B rows, SW64 swizzle), 48KB static.
// ---------------------------------------------------------------------------
template <int NL, int EPI>
__global__ void __launch_bounds__(256, 1)
gemm_mma(const float* __restrict__ A, size_t sA, size_t sA2, int zdA, int lda,
         const float* __restrict__ B, size_t sB, int ldb,
         const float* __restrict__ bias,
         float* __restrict__ C, size_t sC, size_t sC2, int zdC, int ldc,
         int K, float alpha)
{
    __shared__ __align__(128) char sm[49152];   // A planes @0, B planes @24576
    const int t = threadIdx.x;
    const int lane = t & 31, warp = t >> 5;
    const int wm = warp >> 2, wn = warp & 3;    // 2 x 4 warp grid
    const int z = blockIdx.z;
    const int mblk = blockIdx.y * 128, nblk = blockIdx.x * 128;

    const float* Az = A + (size_t)(z / zdA) * sA + (size_t)(z % zdA) * sA2 + (size_t)mblk * lda;
    const float* Bz = B + (size_t)z * sB + (size_t)nblk * ldb;
    float* Cz = C + (size_t)(z / zdC) * sC + (size_t)(z % zdC) * sC2;

    const uint32_t sbase = smem_u32(sm);
    const int lrow = t >> 3;       // 0..31
    const int lk4  = t & 7;        // float4 slot along K(32)

    float4 ra[4], rb[4];
#define LOADTILE(tt) do {                                                      \
        const float* _ap = Az + (tt) * 32 + lk4 * 4;                           \
        const float* _bp = Bz + (tt) * 32 + lk4 * 4;                           \
        _Pragma("unroll")                                                      \
        for (int j = 0; j < 4; j++) {                                          \
            ra[j] = *(const float4*)(_ap + (size_t)(lrow + j * 32) * lda);     \
            rb[j] = *(const float4*)(_bp + (size_t)(lrow + j * 32) * ldb);     \
        }                                                                      \
    } while (0)

    float acc[4][4][4];
#pragma unroll
    for (int mi = 0; mi < 4; mi++)
#pragma unroll
        for (int ni = 0; ni < 4; ni++)
#pragma unroll
            for (int c = 0; c < 4; c++) acc[mi][ni][c] = 0.f;

    // ldmatrix lane->address precompute
    const int a_row = wm * 64 + (lane & 15);
    const int a_kb  = (lane >> 4) << 4;                       // 0 | 16 bytes
    const int b_row = wn * 32 + (lane & 7) + ((lane & 16) ? 8 : 0);
    const int b_kb  = (lane & 8) ? 16 : 0;

    const int T = K >> 5;
    LOADTILE(0);

    for (int tt = 0; tt < T; tt++) {
        __syncthreads();
        // convert + store limb planes
#pragma unroll
        for (int j = 0; j < 4; j++) {
            int row = lrow + j * 32;
            uint32_t off = sw64((uint32_t)(row * 64 + lk4 * 8));
            uint32_t p0, p1, p2, q0, q1, q2;
            split2<NL>(ra[j].x, ra[j].y, p0, p1, p2);
            split2<NL>(ra[j].z, ra[j].w, q0, q1, q2);
            *(uint2*)(sm + off)        = make_uint2(p0, q0);
            *(uint2*)(sm + 8192 + off) = make_uint2(p1, q1);
            if (NL == 3) *(uint2*)(sm + 16384 + off) = make_uint2(p2, q2);
            split2<NL>(rb[j].x, rb[j].y, p0, p1, p2);
            split2<NL>(rb[j].z, rb[j].w, q0, q1, q2);
            *(uint2*)(sm + 24576 + off)        = make_uint2(p0, q0);
            *(uint2*)(sm + 24576 + 8192 + off) = make_uint2(p1, q1);
            if (NL == 3) *(uint2*)(sm + 24576 + 16384 + off) = make_uint2(p2, q2);
        }
        if (tt + 1 < T) LOADTILE(tt + 1);
        __syncthreads();

#pragma unroll
        for (int ks = 0; ks < 2; ks++) {
            const int NP = (NL == 3) ? 6 : 3;
            const int pa[6] = {0, 0, 1, 1, 0, 2};
            const int pb[6] = {0, 1, 0, 1, 2, 0};
#pragma unroll
            for (int p = 0; p < NP; p++) {
                uint32_t afr[4][4];
                uint32_t ab = sbase + pa[p] * 8192;
#pragma unroll
                for (int mi = 0; mi < 4; mi++)
                    ldmx4(afr[mi], ab + sw64((uint32_t)((a_row + mi * 16) * 64 + ks * 32 + a_kb)));
                uint32_t bfr[4][2];
                uint32_t bb = sbase + 24576 + pb[p] * 8192;
#pragma unroll
                for (int nj = 0; nj < 2; nj++) {
                    uint32_t r[4];
                    ldmx4(r, bb + sw64((uint32_t)((b_row + nj * 16) * 64 + ks * 32 + b_kb)));
                    bfr[nj * 2][0] = r[0]; bfr[nj * 2][1] = r[1];
                    bfr[nj * 2 + 1][0] = r[2]; bfr[nj * 2 + 1][1] = r[3];
                }
#pragma unroll
                for (int mi = 0; mi < 4; mi++)
#pragma unroll
                    for (int ni = 0; ni < 4; ni++)
                        mma16816(acc[mi][ni], afr[mi], bfr[ni]);
            }
        }
    }

    // epilogue: direct frag stores (float2 = full 32B sectors)
    const int r0 = mblk + wm * 64 + (lane >> 2);
    const int c0 = nblk + wn * 32 + (lane & 3) * 2;
#pragma unroll
    for (int mi = 0; mi < 4; mi++) {
#pragma unroll
        for (int ni = 0; ni < 4; ni++) {
            int col = c0 + ni * 8;
            float o[4];
#pragma unroll
            for (int c = 0; c < 4; c++) {
                float vv = acc[mi][ni][c];
                if (EPI == 1) vv += __ldg(&bias[col + (c & 1)]);
                else if (EPI == 2) {
                    float ax = fabsf(vv * alpha);
                    float th = 1.f - __fdividef(2.f, __expf(2.f * ax) + 1.f);
                    vv = copysignf(th, vv);
                } else if (EPI == 3) {
                    vv += __ldg(&bias[col + (c & 1)]);
                    vv = vv > 0.f ? vv : 0.f;
                }
                o[c] = vv;
            }
            *(float2*)&Cz[(size_t)(r0 + mi * 16) * ldc + col]     = make_float2(o[0], o[1]);
            *(float2*)&Cz[(size_t)(r0 + mi * 16 + 8) * ldc + col] = make_float2(o[2], o[3]);
        }
    }
#undef LOADTILE
}

// v [b][n][h*128+f] -> vt [z][f][n]
__global__ void transpose_v(const float* __restrict__ v, float* __restrict__ vt) {
    __shared__ float tl[32][33];
    const int z = blockIdx.z, b = z >> 2, h = z & 3;
    const int n0 = blockIdx.x * 32, f0 = blockIdx.y * 32;
    const float* src = v + (size_t)b * NN * 512 + (size_t)h * 128;
    float* dst = vt + (size_t)z * EE * NN;
    const int tx = threadIdx.x, ty = threadIdx.y;
#pragma unroll
    for (int i = 0; i < 32; i += 8)
        tl[ty + i][tx] = src[(size_t)(n0 + ty + i) * 512 + f0 + tx];
    __syncthreads();
#pragma unroll
    for (int i = 0; i < 32; i += 8)
        dst[(size_t)(f0 + ty + i) * NN + n0 + tx] = tl[tx][ty + i];
}

extern "C" void kernel_launch(void* const* d_in, const int* in_sizes, int n_in,
                              void* d_out, int out_size)
{
    const float* x   = (const float*)d_in[0];
    const float* W1  = (const float*)d_in[1];
    const float* b1  = (const float*)d_in[2];
    const float* wqW = (const float*)d_in[3];
    const float* wqb = (const float*)d_in[4];
    const float* wvW = (const float*)d_in[7];
    const float* wvb = (const float*)d_in[8];
    const float* W2  = (const float*)d_in[9];
    const float* b2  = (const float*)d_in[10];
    float* out = (float*)d_out;

    float *info, *emb, *q, *v, *vt, *mt, *attn, *hcat;
    cudaGetSymbolAddress((void**)&info, g_info);
    cudaGetSymbolAddress((void**)&emb,  g_emb);
    cudaGetSymbolAddress((void**)&q,    g_q);
    cudaGetSymbolAddress((void**)&v,    g_v);
    cudaGetSymbolAddress((void**)&vt,   g_vt);
    cudaGetSymbolAddress((void**)&mt,   g_mt);
    cudaGetSymbolAddress((void**)&attn, g_attn);
    cudaGetSymbolAddress((void**)&hcat, g_hcat);

    const float alpha = 0.08838834764831843f;  // 1/sqrt(128)

    // S1: info[b] = x_b @ x_b^T                         K=128
    gemm_mma<3,0><<<dim3(16,16,BB), 256>>>(
        x, (size_t)NN*EE, 0, 1, EE,  x, (size_t)NN*EE, EE,  nullptr,
        info, (size_t)NN*NN, 0, 1, NN,  EE, 0.f);

    // S2: emb[b] = info_b @ W1^T + b1                   K=2048
    gemm_mma<3,1><<<dim3(1,16,BB), 256>>>(
        info, (size_t)NN*NN, 0, 1, NN,  W1, 0, NN,  b1,
        emb, (size_t)NN*EE, 0, 1, EE,  NN, 0.f);

    // S3: q/v (all heads) = emb_b @ Wcat^T + bcat       K=128
    gemm_mma<3,1><<<dim3(4,16,BB), 256>>>(
        emb, (size_t)NN*EE, 0, 1, EE,  wqW, 0, EE,  wqb,
        q, (size_t)NN*512, 0, 1, 512,  EE, 0.f);
    gemm_mma<3,1><<<dim3(4,16,BB), 256>>>(
        emb, (size_t)NN*EE, 0, 1, EE,  wvW, 0, EE,  wvb,
        v, (size_t)NN*512, 0, 1, 512,  EE, 0.f);

    transpose_v<<<dim3(64,4,BB*HH), dim3(32,8)>>>(v, vt);

    // S4: mt[z] = info_b @ vt_z^T  (info symmetric)     K=2048
    gemm_mma<3,0><<<dim3(1,16,BB*HH), 256>>>(
        info, (size_t)NN*NN, 0, HH, NN,  vt, (size_t)EE*NN, NN,  nullptr,
        mt, (size_t)NN*EE, 0, 1, EE,  NN, 0.f);

    // S5: attn[z] = tanh((q_z @ mt_z^T) * alpha)        K=128
    gemm_mma<3,2><<<dim3(16,16,BB*HH), 256>>>(
        q, (size_t)NN*512, 128, HH, 512,  mt, (size_t)NN*EE, EE,  nullptr,
        attn, (size_t)NN*NN, 0, 1, NN,  EE, alpha);

    // S6: hcat[b][n][h*128+f] = attn_z @ vt_z^T         K=2048
    gemm_mma<2,0><<<dim3(1,16,BB*HH), 256>>>(
        attn, (size_t)NN*NN, 0, 1, NN,  vt, (size_t)EE*NN, NN,  nullptr,
        hcat, (size_t)NN*512, 128, HH, 512,  NN, 0.f);

    // S7: out[b] = relu(hcat_b @ W2^T + b2)             K=512
    gemm_mma<2,3><<<dim3(1,16,BB), 256>>>(
        hcat, (size_t)NN*512, 0, 1, 512,  W2, 0, 512,  b2,
        out, (size_t)NN*EE, 0, 1, EE,  512, 0.f);
}